// round 13
// baseline (speedup 1.0000x reference)
#include <cuda_runtime.h>
#include <cuda_bf16.h>

// Problem constants (fixed by the dataset)
#define T_LEN 262144
#define I_DIM 6
#define H_DIM 50      // real hidden size
#define HP2   64      // padded hidden units (pad units identically 0)
#define GP    128     // threads per scan CTA (4 warps): thread = (unit, K-half)

// Chunked-scan parameters: one chunk per resident CTA (2 CTAs/SM x 148 SMs)
#define C_CHUNKS 296
#define S_CHUNK  ((T_LEN + C_CHUNKS - 1) / C_CHUNKS)   // 886 owned steps
#define WARMUP   40                                    // burn-in (926 total: even)

__device__ float g_hs[T_LEN * H_DIM];   // 52 MB; h_t history (L2-hot for fused epilogue)

typedef unsigned long long ull;

// ---------------- packed f32x2 / MUFU helpers ----------------
__device__ __forceinline__ ull pk2(float lo, float hi) {
    ull r; asm("mov.b64 %0, {%1, %2};" : "=l"(r) : "f"(lo), "f"(hi)); return r;
}
__device__ __forceinline__ ull fma2(ull a, ull b, ull c) {
    ull d; asm("fma.rn.f32x2 %0, %1, %2, %3;" : "=l"(d) : "l"(a), "l"(b), "l"(c)); return d;
}
__device__ __forceinline__ ull add2(ull a, ull b) {
    ull d; asm("add.rn.f32x2 %0, %1, %2;" : "=l"(d) : "l"(a), "l"(b)); return d;
}
__device__ __forceinline__ float2 upk(ull v) {
    float2 f; asm("mov.b64 {%0, %1}, %2;" : "=f"(f.x), "=f"(f.y) : "l"(v)); return f;
}
__device__ __forceinline__ float tanhap(float x) {
    float y; asm("tanh.approx.f32 %0, %1;" : "=f"(y) : "f"(x)); return y;
}
__device__ __forceinline__ float hsum(ull v) {
    float2 f = upk(v); return f.x + f.y;
}

// ---------------- Kernel: chunked LSTM scan + fused output head ----------------
// R12: LDS is the measured bottleneck (~5 cyc/LDS-instr per SM). Thread
// p -> j = p/2 (hidden unit), sub = p&1 (K-half). Each thread computes ALL
// FOUR gate rows (i,f,g,o) of unit j over its K-half, so h is loaded ONCE
// per thread per step: 7 LDS/thread, 28 per CTA-step (was 52 in R8).
//   sub==0 -> h pairs 0..11 (cols 0..23) + x pairs 0,1
//   sub==1 -> h pairs 12..23 (cols 24..47) + tail pair 24 + x pair 2 + bias
// (unowned weights ZERO -> warp-uniform stream). K-halves reduced with one
// shfl_xor(1) per gate; carry/hidden update is thread-local (both subs agree).
// ORDERING INVARIANT: xc consumed before the step+2 prefetch overwrites it.
__global__ void __launch_bounds__(GP, 2)
lstm_scan_chunks(const float* __restrict__ X,
                 const float* __restrict__ Wih,
                 const float* __restrict__ Whh,
                 const float* __restrict__ bih,
                 const float* __restrict__ bhh,
                 const float* __restrict__ Wlin,
                 const float* __restrict__ blin,
                 float* __restrict__ out) {
    __shared__ __align__(16) float h_sh[2][HP2];

    const int chunk = blockIdx.x;
    const int own_start = chunk * S_CHUNK;
    const int own_end   = min(own_start + S_CHUNK, T_LEN);
    const int start     = max(0, own_start - WARMUP);
    if (own_start >= T_LEN) return;

    const int tid = threadIdx.x;
    const int j   = tid >> 1;
    const int sub = tid & 1;
    const bool realj = (j < H_DIM);

    // Per-gate weights over the owned K-half: 13 pairs each (slot12 zero on sub0).
    // Gate order in arrays: 0=i, 1=f, 2=g, 3=o. Sigmoid gates pre-scaled by 0.5.
    ull wh[4][13];
    ull wx[4][2];          // sub0 owns x pairs 0,1; sub1 owns x pair 2 (slot0) + zero
    ull bias[4];
#pragma unroll
    for (int gidx = 0; gidx < 4; gidx++) {
        bias[gidx] = 0ull;
#pragma unroll
        for (int m = 0; m < 13; m++) wh[gidx][m] = 0ull;
#pragma unroll
        for (int m = 0; m < 2; m++) wx[gidx][m] = 0ull;
    }
    if (realj) {
#pragma unroll
        for (int gidx = 0; gidx < 4; gidx++) {
            const int r = gidx * H_DIM + j;
            const float sc = (gidx == 2) ? 1.0f : 0.5f;   // tanh gate g unscaled
            const float* wr = Whh + r * H_DIM;
            const int pbase = sub * 12;
#pragma unroll
            for (int m = 0; m < 12; m++) {
                int gp = pbase + m;
                wh[gidx][m] = pk2(sc * __ldg(&wr[2 * gp]), sc * __ldg(&wr[2 * gp + 1]));
            }
            const float* wxr = Wih + r * I_DIM;
            if (sub == 1) {
                wh[gidx][12] = pk2(sc * __ldg(&wr[48]), sc * __ldg(&wr[49]));
                wx[gidx][0]  = pk2(sc * __ldg(&wxr[4]), sc * __ldg(&wxr[5]));  // x pair 2
                bias[gidx]   = pk2(sc * (__ldg(&bih[r]) + __ldg(&bhh[r])), 0.0f);
            } else {
                wx[gidx][0]  = pk2(sc * __ldg(&wxr[0]), sc * __ldg(&wxr[1]));  // x pair 0
                wx[gidx][1]  = pk2(sc * __ldg(&wxr[2]), sc * __ldg(&wxr[3]));  // x pair 1
            }
        }
    }

    float c = 0.0f;
    if (tid < HP2) { h_sh[0][tid] = 0.0f; h_sh[1][tid] = 0.0f; }

    // depth-2 x prefetch: xq{0,1} hold this thread's owned x pairs for t, t+1.
    //   sub0 uses slots {0,1} = x pairs 0,1 ; sub1 uses slot {0} = x pair 2
    ull xq0[2], xq1[2];
    {
        const float2* x0 = (const float2*)(X + (size_t)start * I_DIM);
        const float2* x1 = (const float2*)(X + (size_t)(start + 1) * I_DIM);
        if (sub == 1) {
            float2 v0 = __ldg(&x0[2]); xq0[0] = pk2(v0.x, v0.y); xq0[1] = 0ull;
            float2 v1 = __ldg(&x1[2]); xq1[0] = pk2(v1.x, v1.y); xq1[1] = 0ull;
        } else {
            float2 a0 = __ldg(&x0[0]), b0 = __ldg(&x0[1]);
            xq0[0] = pk2(a0.x, a0.y); xq0[1] = pk2(b0.x, b0.y);
            float2 a1 = __ldg(&x1[0]), b1 = __ldg(&x1[1]);
            xq1[0] = pk2(a1.x, a1.y); xq1[1] = pk2(b1.x, b1.y);
        }
    }

    __syncthreads();

    for (int t = start; t < own_end; t += 2) {
#pragma unroll
        for (int p = 0; p < 2; p++) {
            const int step = t + p;
            ull* xc = p ? xq1 : xq0;

            // (1) x-part + bias — consumes xc (uniform: zero weights where unowned)
            ull aI0 = fma2(wx[0][0], xc[0], bias[0]);
            ull aF0 = fma2(wx[1][0], xc[0], bias[1]);
            ull aG0 = fma2(wx[2][0], xc[0], bias[2]);
            ull aO0 = fma2(wx[3][0], xc[0], bias[3]);
            ull aI1 = fma2(wx[0][1], xc[1], 0ull);
            ull aF1 = fma2(wx[1][1], xc[1], 0ull);
            ull aG1 = fma2(wx[2][1], xc[1], 0ull);
            ull aO1 = fma2(wx[3][1], xc[1], 0ull);

            // (2) prefetch owned x slice of step+2 — AFTER xc consumed
            if (step + 2 < own_end) {
                const float2* xn = (const float2*)(X + (size_t)(step + 2) * I_DIM);
                if (sub == 1) {
                    float2 v = __ldg(&xn[2]); xc[0] = pk2(v.x, v.y);
                } else {
                    float2 a = __ldg(&xn[0]), b = __ldg(&xn[1]);
                    xc[0] = pk2(a.x, a.y); xc[1] = pk2(b.x, b.y);
                }
            }

            // (3) h-matvec over owned half: 6x LDS.128 + 1x LDS.64, feeds 4 rows
            const float* hb = h_sh[step & 1];
            const ulonglong2* h8 = (const ulonglong2*)(hb + sub * 24);
#pragma unroll
            for (int q = 0; q < 6; q++) {
                ulonglong2 v = h8[q];
                aI0 = fma2(wh[0][2 * q],     v.x, aI0);
                aI1 = fma2(wh[0][2 * q + 1], v.y, aI1);
                aF0 = fma2(wh[1][2 * q],     v.x, aF0);
                aF1 = fma2(wh[1][2 * q + 1], v.y, aF1);
                aG0 = fma2(wh[2][2 * q],     v.x, aG0);
                aG1 = fma2(wh[2][2 * q + 1], v.y, aG1);
                aO0 = fma2(wh[3][2 * q],     v.x, aO0);
                aO1 = fma2(wh[3][2 * q + 1], v.y, aO1);
            }
            {
                ull vt = *(const ull*)(hb + 48);   // cols 48,49 (weights zero on sub0)
                aI0 = fma2(wh[0][12], vt, aI0);
                aF0 = fma2(wh[1][12], vt, aF0);
                aG0 = fma2(wh[2][12], vt, aG0);
                aO0 = fma2(wh[3][12], vt, aO0);
            }
            float pI = hsum(add2(aI0, aI1));
            float pF = hsum(add2(aF0, aF1));
            float pG = hsum(add2(aG0, aG1));
            float pO = hsum(add2(aO0, aO1));

            // (4) K-half reduction (partner = lane^1)
            pI += __shfl_xor_sync(0xffffffffu, pI, 1);
            pF += __shfl_xor_sync(0xffffffffu, pF, 1);
            pG += __shfl_xor_sync(0xffffffffu, pG, 1);
            pO += __shfl_xor_sync(0xffffffffu, pO, 1);

            // (5) activations (scales pre-folded): i,f,o sigmoid; g tanh
            float vi = fmaf(0.5f, tanhap(pI), 0.5f);
            float vf = fmaf(0.5f, tanhap(pF), 0.5f);
            float vg = tanhap(pG);
            float vo = fmaf(0.5f, tanhap(pO), 0.5f);

            // (6) carry + hidden update — thread-local (both subs identical)
            c = fmaf(vf, c, vi * vg);
            float hn = vo * tanhap(c);

            if (sub == 0) {
                h_sh[(step + 1) & 1][j] = hn;                       // next step's input
                if (realj && step >= own_start && step < own_end)
                    g_hs[(size_t)step * H_DIM + j] = hn;            // owned history
            }
            __syncthreads();
        }
    }

    // ---- fused output head over this chunk's owned steps (g_hs is L2-hot) ----
    __syncthreads();
    const float b0 = __ldg(&blin[0]);
    for (int t = own_start + tid; t < own_end; t += GP) {
        const float2* h2 = (const float2*)(g_hs + (size_t)t * H_DIM);
        float acc = b0;
#pragma unroll
        for (int m = 0; m < H_DIM / 2; m++) {
            float2 hv = h2[m];
            float2 wv = __ldg(&((const float2*)Wlin)[m]);
            acc = fmaf(hv.x, wv.x, fmaf(hv.y, wv.y, acc));
        }
        out[t] = 1.0f / (1.0f + __expf(-acc));
    }
}

// ---------------- launch ----------------
extern "C" void kernel_launch(void* const* d_in, const int* in_sizes, int n_in,
                              void* d_out, int out_size) {
    const float* X    = (const float*)d_in[0];
    const float* Wih  = (const float*)d_in[1];
    const float* Whh  = (const float*)d_in[2];
    const float* bih  = (const float*)d_in[3];
    const float* bhh  = (const float*)d_in[4];
    const float* Wlin = (const float*)d_in[5];
    const float* blin = (const float*)d_in[6];
    float* out = (float*)d_out;

    lstm_scan_chunks<<<C_CHUNKS, GP>>>(X, Wih, Whh, bih, bhh, Wlin, blin, out);
}

// round 15
// speedup vs baseline: 1.3233x; 1.3233x over previous
#include <cuda_runtime.h>
#include <cuda_bf16.h>

// Problem constants (fixed by the dataset)
#define T_LEN 262144
#define I_DIM 6
#define H_DIM 50      // real hidden size
#define HP2   64      // padded hidden units (pad units identically 0)
#define GP    128     // 2*HP2 threads per scan CTA (4 warps): thread=(unit, gate-pair)

// Chunked-scan parameters: one chunk per resident CTA (2 CTAs/SM x 148 SMs)
#define C_CHUNKS 296
#define S_CHUNK  ((T_LEN + C_CHUNKS - 1) / C_CHUNKS)   // 886 owned steps
#define WARMUP   40                                    // burn-in (926 total: even)

// Phase stagger (cycles) applied to the second co-resident wave (bid >= 148)
#define STAGGER_CYC 700ull

__device__ float g_hs[T_LEN * H_DIM];   // 52 MB; h_t history (L2-hot for fused epilogue)

typedef unsigned long long ull;

// ---------------- packed f32x2 / MUFU helpers ----------------
__device__ __forceinline__ ull pk2(float lo, float hi) {
    ull r; asm("mov.b64 %0, {%1, %2};" : "=l"(r) : "f"(lo), "f"(hi)); return r;
}
__device__ __forceinline__ ull fma2(ull a, ull b, ull c) {
    ull d; asm("fma.rn.f32x2 %0, %1, %2, %3;" : "=l"(d) : "l"(a), "l"(b), "l"(c)); return d;
}
__device__ __forceinline__ ull add2(ull a, ull b) {
    ull d; asm("add.rn.f32x2 %0, %1, %2;" : "=l"(d) : "l"(a), "l"(b)); return d;
}
__device__ __forceinline__ float2 upk(ull v) {
    float2 f; asm("mov.b64 {%0, %1}, %2;" : "=f"(f.x), "=f"(f.y) : "l"(v)); return f;
}
__device__ __forceinline__ float tanhap(float x) {
    float y; asm("tanh.approx.f32 %0, %1;" : "=f"(y) : "f"(x)); return y;
}

// ---------------- Kernel: chunked LSTM scan + fused output head ----------------
// R8 structure (best known): thread p -> j = p/2 (unit), k2 = p%2 (gate pair).
//   k2==0 -> rows i (0H+j), f (1H+j);   k2==1 -> rows g (2H+j), o (3H+j)
// h loaded once per step feeds both rows; one shfl_xor(1) exchanges (g,o)->(i,f).
// R13/R14 delta: one-time ~700-cycle spin for the second co-resident wave
// (bid >= 148) to desynchronize the two CTAs sharing each SM, so their
// post-barrier LDS/FMA bursts interleave instead of colliding.
__global__ void __launch_bounds__(GP, 2)
lstm_scan_chunks(const float* __restrict__ X,
                 const float* __restrict__ Wih,
                 const float* __restrict__ Whh,
                 const float* __restrict__ bih,
                 const float* __restrict__ bhh,
                 const float* __restrict__ Wlin,
                 const float* __restrict__ blin,
                 float* __restrict__ out) {
    __shared__ __align__(16) float h_sh[2][HP2];

    const int chunk = blockIdx.x;
    const int own_start = chunk * S_CHUNK;
    const int own_end   = min(own_start + S_CHUNK, T_LEN);
    const int start     = max(0, own_start - WARMUP);
    if (own_start >= T_LEN) return;

    const int tid = threadIdx.x;
    const int j   = tid >> 1;
    const int k2  = tid & 1;
    const bool realj = (j < H_DIM);

    // Row A: k2==0 -> i (sigmoid), k2==1 -> g (tanh)
    // Row B: k2==0 -> f (sigmoid), k2==1 -> o (sigmoid)
    const int   rA  = (k2 == 0) ? (0 * H_DIM + j) : (2 * H_DIM + j);
    const int   rB  = (k2 == 0) ? (1 * H_DIM + j) : (3 * H_DIM + j);
    const float sA  = (k2 == 0) ? 0.5f : 1.0f;   // folded gate-input scale
    const float sB  = 0.5f;
    const float AaA = (k2 == 0) ? 0.5f : 1.0f;   // affine after tanh
    const float BbA = (k2 == 0) ? 0.5f : 0.0f;

    // Register-resident pre-scaled weights (zeros for pad units)
    ull whA[H_DIM / 2], whB[H_DIM / 2];   // 25 + 25 packed pairs
    ull wxA[I_DIM / 2], wxB[I_DIM / 2];   // 3 + 3 packed pairs
    ull biasA = 0ull, biasB = 0ull;
#pragma unroll
    for (int m = 0; m < H_DIM / 2; m++) { whA[m] = 0ull; whB[m] = 0ull; }
#pragma unroll
    for (int m = 0; m < I_DIM / 2; m++) { wxA[m] = 0ull; wxB[m] = 0ull; }
    if (realj) {
        const float* wrA = Whh + rA * H_DIM;
        const float* wrB = Whh + rB * H_DIM;
#pragma unroll
        for (int m = 0; m < H_DIM / 2; m++) {
            whA[m] = pk2(sA * __ldg(&wrA[2 * m]), sA * __ldg(&wrA[2 * m + 1]));
            whB[m] = pk2(sB * __ldg(&wrB[2 * m]), sB * __ldg(&wrB[2 * m + 1]));
        }
        const float* wxa = Wih + rA * I_DIM;
        const float* wxb = Wih + rB * I_DIM;
#pragma unroll
        for (int m = 0; m < I_DIM / 2; m++) {
            wxA[m] = pk2(sA * __ldg(&wxa[2 * m]), sA * __ldg(&wxa[2 * m + 1]));
            wxB[m] = pk2(sB * __ldg(&wxb[2 * m]), sB * __ldg(&wxb[2 * m + 1]));
        }
        biasA = pk2(sA * (__ldg(&bih[rA]) + __ldg(&bhh[rA])), 0.0f);
        biasB = pk2(sB * (__ldg(&bih[rB]) + __ldg(&bhh[rB])), 0.0f);
    }

    float c = 0.0f;
    if (tid < HP2) { h_sh[0][tid] = 0.0f; h_sh[1][tid] = 0.0f; }

    // depth-2 x prefetch: xp{0,1} hold x[t], x[t+1] packed as 3 f32x2 each
    ull xp0[3], xp1[3];
    {
        const float2* x0 = (const float2*)(X + (size_t)start * I_DIM);
#pragma unroll
        for (int m = 0; m < 3; m++) { float2 v = __ldg(&x0[m]); xp0[m] = pk2(v.x, v.y); }
        const float2* x1 = (const float2*)(X + (size_t)(start + 1) * I_DIM);
#pragma unroll
        for (int m = 0; m < 3; m++) { float2 v = __ldg(&x1[m]); xp1[m] = pk2(v.x, v.y); }
    }

    __syncthreads();

    // Desynchronize co-resident CTA pairs (bid, bid+148). One-time spin;
    // the phase offset persists because both CTAs have identical per-step cost.
    if (chunk >= 148) {
        unsigned long long t0 = clock64();
        while (clock64() - t0 < STAGGER_CYC) { }
    }
    __syncthreads();

    for (int t = start; t < own_end; t += 2) {
#pragma unroll
        for (int p = 0; p < 2; p++) {
            const int step = t + p;
            ull* xc = p ? xp1 : xp0;

            // (1) x-part + bias — consumes xc BEFORE the prefetch clobbers it
            ull aA0 = fma2(wxA[0], xc[0], biasA);
            ull aA1 = fma2(wxA[1], xc[1], 0ull);
            ull aB0 = fma2(wxB[0], xc[0], biasB);
            ull aB1 = fma2(wxB[1], xc[1], 0ull);
            aA0 = fma2(wxA[2], xc[2], aA0);
            aB0 = fma2(wxB[2], xc[2], aB0);

            // (2) prefetch x[step+2] (off critical path)
            if (step + 2 < own_end) {
                const float2* xn = (const float2*)(X + (size_t)(step + 2) * I_DIM);
#pragma unroll
                for (int m = 0; m < 3; m++) { float2 v = __ldg(&xn[m]); xc[m] = pk2(v.x, v.y); }
            }

            // (3) h-matvec: h loaded ONCE (12 LDS.128 + 1 LDS.64), feeds BOTH rows
            const float* hb = h_sh[step & 1];
            const ulonglong2* h8 = (const ulonglong2*)hb;
#pragma unroll
            for (int q = 0; q < 12; q++) {
                ulonglong2 v = h8[q];
                aA0 = fma2(whA[2 * q],     v.x, aA0);
                aA1 = fma2(whA[2 * q + 1], v.y, aA1);
                aB0 = fma2(whB[2 * q],     v.x, aB0);
                aB1 = fma2(whB[2 * q + 1], v.y, aB1);
            }
            {
                ull vt = *(const ull*)(hb + 48);      // cols 48,49
                aA0 = fma2(whA[24], vt, aA0);
                aB0 = fma2(whB[24], vt, aB0);
            }
            float2 fA = upk(add2(aA0, aA1));
            float2 fB = upk(add2(aB0, aB1));
            float preA = fA.x + fA.y;
            float preB = fB.x + fB.y;

            // (4) activations: rowA = i or g; rowB = f or o
            float valA = fmaf(AaA, tanhap(preA), BbA);
            float valB = fmaf(0.5f, tanhap(preB), 0.5f);

            // (5) gate-pair exchange: even thread gets (g,o)
            float vg = __shfl_xor_sync(0xffffffffu, valA, 1);
            float vo = __shfl_xor_sync(0xffffffffu, valB, 1);

            // (6) carry + hidden update (even thread authoritative; pads stay 0)
            c = fmaf(valB, c, valA * vg);
            float hn = vo * tanhap(c);

            if (k2 == 0) {
                h_sh[(step + 1) & 1][j] = hn;                       // next step's input
                if (realj && step >= own_start && step < own_end)
                    g_hs[(size_t)step * H_DIM + j] = hn;            // owned history
            }
            __syncthreads();
        }
    }

    // ---- fused output head over this chunk's owned steps (g_hs is L2-hot) ----
    __syncthreads();
    const float b0 = __ldg(&blin[0]);
    for (int t = own_start + tid; t < own_end; t += GP) {
        const float2* h2 = (const float2*)(g_hs + (size_t)t * H_DIM);
        float acc = b0;
#pragma unroll
        for (int m = 0; m < H_DIM / 2; m++) {
            float2 hv = h2[m];
            float2 wv = __ldg(&((const float2*)Wlin)[m]);
            acc = fmaf(hv.x, wv.x, fmaf(hv.y, wv.y, acc));
        }
        out[t] = 1.0f / (1.0f + __expf(-acc));
    }
}

// ---------------- launch ----------------
extern "C" void kernel_launch(void* const* d_in, const int* in_sizes, int n_in,
                              void* d_out, int out_size) {
    const float* X    = (const float*)d_in[0];
    const float* Wih  = (const float*)d_in[1];
    const float* Whh  = (const float*)d_in[2];
    const float* bih  = (const float*)d_in[3];
    const float* bhh  = (const float*)d_in[4];
    const float* Wlin = (const float*)d_in[5];
    const float* blin = (const float*)d_in[6];
    float* out = (float*)d_out;

    lstm_scan_chunks<<<C_CHUNKS, GP>>>(X, Wih, Whh, bih, bhh, Wlin, blin, out);
}